// round 14
// baseline (speedup 1.0000x reference)
#include <cuda_runtime.h>
#include <cuda_fp16.h>
#include <cstdint>

// ---------------------------------------------------------------------------
// ConversationalGraph: 2x GraphConv (D=H=64) + leaky_relu + mean-pool + linear
//   layer: out = segsum(x[src]*w -> dst) @ W_rel + b + x @ W_root
// N=100000, E=1250000, 512 graphs, C=8.
// CSR counting-sort + FUSED gather+GEMM layer kernel:
//   each 128-row block gathers its agg tile into smem (transposed), then runs
//   the f32x2 packed-FMA GEMM reading the rel operand straight from smem.
// Layer-1 features fp32 (input x), layer-2 features fp16 (h1).
// ---------------------------------------------------------------------------

#define NMAX   100000
#define EMAX   1250000
#define DIM    64
#define NGRAPH 512
#define SCANB  1024
#define NBLK   ((NMAX + SCANB - 1) / SCANB)   // 98

__device__ __half g_h1h[NMAX * DIM];
__device__ float  g_pooled[NGRAPH * DIM];
__device__ float  g_counts[NGRAPH];

__device__ alignas(16) int2 g_edges[EMAX];   // (src, w-bits) sorted by dst
__device__ int  g_deg[NMAX];
__device__ int  g_rowstart[NMAX + 1];
__device__ int  g_cursor[NMAX];
__device__ int  g_blocksum[NBLK + 1];

// ---- packed f32x2 helpers --------------------------------------------------
__device__ __forceinline__ uint64_t ffma2(uint64_t a, uint64_t b, uint64_t c) {
    uint64_t d;
    asm("fma.rn.f32x2 %0, %1, %2, %3;" : "=l"(d) : "l"(a), "l"(b), "l"(c));
    return d;
}
__device__ __forceinline__ uint64_t splat2(float f) {
    uint64_t d;
    asm("mov.b64 %0, {%1, %1};" : "=l"(d) : "f"(f));
    return d;
}
__device__ __forceinline__ void unpack2(uint64_t v, float& lo, float& hi) {
    asm("mov.b64 {%0, %1}, %2;" : "=f"(lo), "=f"(hi) : "l"(v));
}

// ---------------------------------------------------------------------------
__global__ void zero_kernel(int* deg, float* pooled, float* counts, int N) {
    int i = blockIdx.x * blockDim.x + threadIdx.x;
    if (i < N) deg[i] = 0;
    if (i < NGRAPH * DIM) pooled[i] = 0.f;
    if (i < NGRAPH) counts[i] = 0.f;
}

// ---------------------------------------------------------------------------
// CSR build: histogram, scan (block-level + fold), scatter (+graph counts)
// ---------------------------------------------------------------------------
__global__ void hist_kernel(const int* __restrict__ ei, int* __restrict__ deg, int E) {
    int e = blockIdx.x * blockDim.x + threadIdx.x;
    if (e < E) atomicAdd(&deg[__ldg(&ei[e + E])], 1);
}

__global__ void scan1_kernel(const int* __restrict__ deg, int* __restrict__ rowstart,
                             int* __restrict__ blocksum, int N) {
    __shared__ int s[SCANB];
    int i = blockIdx.x * SCANB + threadIdx.x;
    int v = (i < N) ? deg[i] : 0;
    s[threadIdx.x] = v;
    __syncthreads();
#pragma unroll
    for (int off = 1; off < SCANB; off <<= 1) {
        int t = (threadIdx.x >= off) ? s[threadIdx.x - off] : 0;
        __syncthreads();
        s[threadIdx.x] += t;
        __syncthreads();
    }
    if (i < N) rowstart[i] = s[threadIdx.x] - v;   // exclusive within block
    if (threadIdx.x == SCANB - 1) blocksum[blockIdx.x] = s[SCANB - 1];
}

__global__ void scan3_kernel(int* __restrict__ rowstart, int* __restrict__ cursor,
                             const int* __restrict__ blocksum, int N, int E, int nb) {
    __shared__ int s[128];
    const int t = threadIdx.x;
    if (t < 128) {
        s[t] = (t > 0 && t - 1 < nb) ? blocksum[t - 1] : 0;
    }
    __syncthreads();
#pragma unroll
    for (int off = 1; off < 128; off <<= 1) {
        int u = (t < 128 && t >= off) ? s[t - off] : 0;
        __syncthreads();
        if (t < 128) s[t] += u;
        __syncthreads();
    }
    int i = blockIdx.x * blockDim.x + t;
    if (i < N) {
        int r = rowstart[i] + s[i >> 10];
        rowstart[i] = r;
        cursor[i] = r;
    }
    if (i == 0) rowstart[N] = E;
}

__global__ void scatter_kernel(const int* __restrict__ ei, const float* __restrict__ w,
                               int* __restrict__ cursor, int2* __restrict__ edges,
                               const int* __restrict__ batch, float* __restrict__ counts,
                               int E, int N) {
    int e = blockIdx.x * blockDim.x + threadIdx.x;
    if (e >= E) return;
    int s = __ldg(&ei[e]);
    int d = __ldg(&ei[e + E]);
    int pos = atomicAdd(&cursor[d], 1);
    edges[pos] = make_int2(s, __float_as_int(__ldg(&w[e])));
    if (e < N) atomicAdd(&counts[__ldg(&batch[e])], 1.0f);   // fused graph counts
}

// ---------------------------------------------------------------------------
// FUSED layer kernel:
//   phase 1 (gather): each warp aggregates 16 nodes' incident edges into the
//     smem tile Ag[64][AGS] laid out [k][row] (lane covers cols 2l, 2l+1).
//   phase 2 (GEMM):  res = leaky( Ag @ Wrel + feat @ Wroot + b ) with packed
//     fma.rn.f32x2; rel operand read straight from Ag, root operand staged
//     through As per 16-wide K chunk.
//   pool==0: store half feature rows (outh); pool==1: fp32 atomic mean-pool
//   accumulation into pooled[batch[row]].
// HALF selects fp16 (h1) vs fp32 (x) feature reads.
// ---------------------------------------------------------------------------
#define AGS 138   // Ag row stride (even for LDS.64 alignment, 4-way STS ok)
#define ASS 132   // As row stride

template <bool HALF>
__global__ void __launch_bounds__(256, 2)
layer_kernel(const void* __restrict__ feat_,
             const int2* __restrict__ edges, const int* __restrict__ rowstart,
             const float* __restrict__ Wrel, const float* __restrict__ Wroot,
             const float* __restrict__ bias,
             __half* __restrict__ outh,
             const int* __restrict__ batch,
             float* __restrict__ pooled,
             int N, int pool) {
    __shared__ float Ag[64][AGS];   // gathered rel operand, [k][row]
    __shared__ float As[16][ASS];   // root operand chunk,   [k][row]
    __shared__ float Ws[16][64];    // weight chunk,         [k][col]

    const int tid = threadIdx.x;
    const int wid = tid >> 5;
    const int lane = tid & 31;
    const int rowBase = blockIdx.x * 128;

    const float*  featf = reinterpret_cast<const float*>(feat_);
    const __half* feath = reinterpret_cast<const __half*>(feat_);

    // ---------------- phase 1: gather into Ag ----------------
#pragma unroll 1
    for (int j = 0; j < 16; j++) {
        const int nl = wid * 16 + j;
        const int node = rowBase + nl;
        float a0 = 0.f, a1 = 0.f;
        if (node < N) {
            int beg = __ldg(&rowstart[node]);
            int end = __ldg(&rowstart[node + 1]);
#pragma unroll 4
            for (int i = beg; i < end; i++) {
                int2 ed = __ldg(&edges[i]);            // broadcast across warp
                float wt = __int_as_float(ed.y);
                float2 xv;
                if (HALF) {
                    __half2 hv = __ldg(reinterpret_cast<const __half2*>(
                        feath + (size_t)ed.x * DIM) + lane);
                    xv = __half22float2(hv);
                } else {
                    xv = __ldg(reinterpret_cast<const float2*>(
                        featf + (size_t)ed.x * DIM) + lane);
                }
                a0 += wt * xv.x;
                a1 += wt * xv.y;
            }
        }
        Ag[2 * lane + 0][nl] = a0;
        Ag[2 * lane + 1][nl] = a1;
    }
    __syncthreads();

    // ---------------- phase 2: GEMM ----------------
    const int tx = tid & 15;        // col group: cols tx*4 .. +3
    const int ty = tid >> 4;        // row group: rows ty*8 .. +7
    const int lr  = tid >> 1;       // As fill row 0..127
    const int lks = (tid & 1) * 8;  // As fill k offset {0,8}
    const int wk = tid >> 4;        // Ws fill
    const int wj = (tid & 15) * 4;

    uint64_t accp[4][4];            // [row-pair][col]
#pragma unroll
    for (int p = 0; p < 4; p++)
#pragma unroll
        for (int c = 0; c < 4; c++) accp[p][c] = 0ull;

#pragma unroll
    for (int kc = 0; kc < 8; kc++) {
        const int kk = (kc & 3) * 16;
        const float* Wsrc = (kc < 4) ? Wrel : Wroot;

        // stage root-operand chunk (only for kc >= 4)
        float4 av0 = make_float4(0.f, 0.f, 0.f, 0.f);
        float4 av1 = av0;
        if (kc >= 4) {
            const int arow = rowBase + lr;
            if (arow < N) {
                if (HALF) {
                    const __half2* base = reinterpret_cast<const __half2*>(
                        feath + (size_t)arow * DIM + kk + lks);
                    __half2 h[4];
                    *reinterpret_cast<uint4*>(h) =
                        *reinterpret_cast<const uint4*>(base);   // 8 halves
                    float2 f0 = __half22float2(h[0]);
                    float2 f1 = __half22float2(h[1]);
                    float2 f2 = __half22float2(h[2]);
                    float2 f3 = __half22float2(h[3]);
                    av0 = make_float4(f0.x, f0.y, f1.x, f1.y);
                    av1 = make_float4(f2.x, f2.y, f3.x, f3.y);
                } else {
                    const float* base = featf + (size_t)arow * DIM + kk + lks;
                    av0 = *reinterpret_cast<const float4*>(base);
                    av1 = *reinterpret_cast<const float4*>(base + 4);
                }
            }
        }
        float4 wv = *reinterpret_cast<const float4*>(Wsrc + (wk + kk) * DIM + wj);

        __syncthreads();
        if (kc >= 4) {
            As[lks + 0][lr] = av0.x;
            As[lks + 1][lr] = av0.y;
            As[lks + 2][lr] = av0.z;
            As[lks + 3][lr] = av0.w;
            As[lks + 4][lr] = av1.x;
            As[lks + 5][lr] = av1.y;
            As[lks + 6][lr] = av1.z;
            As[lks + 7][lr] = av1.w;
        }
        *reinterpret_cast<float4*>(&Ws[wk][wj]) = wv;
        __syncthreads();

#pragma unroll
        for (int k = 0; k < 16; k++) {
            const float* arow_f = (kc < 4) ? &Ag[kk + k][ty * 8]
                                           : &As[k][ty * 8];
            const uint64_t* arow2 = reinterpret_cast<const uint64_t*>(arow_f);
            uint64_t ap0 = arow2[0];
            uint64_t ap1 = arow2[1];
            uint64_t ap2 = arow2[2];
            uint64_t ap3 = arow2[3];
            float4 wq = *reinterpret_cast<float4*>(&Ws[k][tx * 4]);
            uint64_t w0 = splat2(wq.x);
            uint64_t w1 = splat2(wq.y);
            uint64_t w2 = splat2(wq.z);
            uint64_t w3 = splat2(wq.w);
            accp[0][0] = ffma2(ap0, w0, accp[0][0]);
            accp[0][1] = ffma2(ap0, w1, accp[0][1]);
            accp[0][2] = ffma2(ap0, w2, accp[0][2]);
            accp[0][3] = ffma2(ap0, w3, accp[0][3]);
            accp[1][0] = ffma2(ap1, w0, accp[1][0]);
            accp[1][1] = ffma2(ap1, w1, accp[1][1]);
            accp[1][2] = ffma2(ap1, w2, accp[1][2]);
            accp[1][3] = ffma2(ap1, w3, accp[1][3]);
            accp[2][0] = ffma2(ap2, w0, accp[2][0]);
            accp[2][1] = ffma2(ap2, w1, accp[2][1]);
            accp[2][2] = ffma2(ap2, w2, accp[2][2]);
            accp[2][3] = ffma2(ap2, w3, accp[2][3]);
            accp[3][0] = ffma2(ap3, w0, accp[3][0]);
            accp[3][1] = ffma2(ap3, w1, accp[3][1]);
            accp[3][2] = ffma2(ap3, w2, accp[3][2]);
            accp[3][3] = ffma2(ap3, w3, accp[3][3]);
        }
    }

    const float4 b4 = *reinterpret_cast<const float4*>(bias + tx * 4);
#pragma unroll
    for (int p = 0; p < 4; p++) {
        float lo[4], hi[4];
#pragma unroll
        for (int c = 0; c < 4; c++) unpack2(accp[p][c], lo[c], hi[c]);

#pragma unroll
        for (int h = 0; h < 2; h++) {
            const int r = rowBase + ty * 8 + 2 * p + h;
            if (r >= N) continue;
            const float* src = h ? hi : lo;
            float v0 = src[0] + b4.x;
            float v1 = src[1] + b4.y;
            float v2 = src[2] + b4.z;
            float v3 = src[3] + b4.w;
            v0 = (v0 > 0.f) ? v0 : 0.01f * v0;
            v1 = (v1 > 0.f) ? v1 : 0.01f * v1;
            v2 = (v2 > 0.f) ? v2 : 0.01f * v2;
            v3 = (v3 > 0.f) ? v3 : 0.01f * v3;
            if (!pool) {
                __half2 h01 = __floats2half2_rn(v0, v1);
                __half2 h23 = __floats2half2_rn(v2, v3);
                uint2 packed = make_uint2(
                    *reinterpret_cast<uint32_t*>(&h01),
                    *reinterpret_cast<uint32_t*>(&h23));
                *reinterpret_cast<uint2*>(outh + (size_t)r * DIM + tx * 4) = packed;
            } else {
                int g = batch[r];
                float4 v = make_float4(v0, v1, v2, v3);
                atomicAdd(reinterpret_cast<float4*>(pooled + (size_t)g * DIM + tx * 4), v);
            }
        }
    }
}

// ---------------------------------------------------------------------------
__global__ void final_kernel(const float* __restrict__ pooled,
                             const float* __restrict__ counts,
                             const float* __restrict__ Wl,
                             const float* __restrict__ bl,
                             float* __restrict__ out) {
    int g = blockIdx.x * blockDim.x + threadIdx.x;
    if (g >= NGRAPH) return;
    float inv = 1.0f / fmaxf(counts[g], 1.0f);
    float acc[8];
#pragma unroll
    for (int c = 0; c < 8; c++) acc[c] = 0.f;
    for (int d = 0; d < DIM; d++) {
        float p = pooled[g * DIM + d];
#pragma unroll
        for (int c = 0; c < 8; c++) acc[c] += p * Wl[d * 8 + c];
    }
#pragma unroll
    for (int c = 0; c < 8; c++) out[g * 8 + c] = bl[c] + inv * acc[c];
}

// ---------------------------------------------------------------------------
extern "C" void kernel_launch(void* const* d_in, const int* in_sizes, int n_in,
                              void* d_out, int out_size) {
    const float* x      = (const float*)d_in[0];
    const int*   ei     = (const int*)d_in[1];
    const float* w      = (const float*)d_in[2];
    const int*   batch  = (const int*)d_in[3];
    const float* W1root = (const float*)d_in[4];
    const float* W1rel  = (const float*)d_in[5];
    const float* b1     = (const float*)d_in[6];
    const float* W2root = (const float*)d_in[7];
    const float* W2rel  = (const float*)d_in[8];
    const float* b2     = (const float*)d_in[9];
    const float* Wl     = (const float*)d_in[10];
    const float* bl     = (const float*)d_in[11];
    float* out = (float*)d_out;

    const int N = in_sizes[0] / DIM;
    const int E = in_sizes[2];

    float *pooled, *counts;
    __half* h1h;
    int2* edges; int *deg, *rowstart, *cursor, *blocksum;
    cudaGetSymbolAddress((void**)&h1h,      g_h1h);
    cudaGetSymbolAddress((void**)&pooled,   g_pooled);
    cudaGetSymbolAddress((void**)&counts,   g_counts);
    cudaGetSymbolAddress((void**)&edges,    g_edges);
    cudaGetSymbolAddress((void**)&deg,      g_deg);
    cudaGetSymbolAddress((void**)&rowstart, g_rowstart);
    cudaGetSymbolAddress((void**)&cursor,   g_cursor);
    cudaGetSymbolAddress((void**)&blocksum, g_blocksum);

    const int nb = (N + SCANB - 1) / SCANB;

    // ---- CSR build (shared by both layers) ----
    zero_kernel<<<(N + 255) / 256, 256>>>(deg, pooled, counts, N);
    hist_kernel<<<(E + 255) / 256, 256>>>(ei, deg, E);
    scan1_kernel<<<nb, SCANB>>>(deg, rowstart, blocksum, N);
    scan3_kernel<<<(N + 255) / 256, 256>>>(rowstart, cursor, blocksum, N, E, nb);
    scatter_kernel<<<(E + 255) / 256, 256>>>(ei, w, cursor, edges, batch, counts, E, N);

    const int nodeBlocks = (N + 127) / 128;

    // ---- Layer 1 (fp32 features), Layer 2 (fp16 features, pool epilogue) ----
    layer_kernel<false><<<nodeBlocks, 256>>>(x, edges, rowstart,
                                             W1rel, W1root, b1,
                                             h1h, nullptr, nullptr, N, 0);
    layer_kernel<true><<<nodeBlocks, 256>>>(h1h, edges, rowstart,
                                            W2rel, W2root, b2,
                                            nullptr, batch, pooled, N, 1);

    final_kernel<<<(NGRAPH + 255) / 256, 256>>>(pooled, counts, Wl, bl, out);
}

// round 15
// speedup vs baseline: 1.2987x; 1.2987x over previous
#include <cuda_runtime.h>
#include <cuda_fp16.h>
#include <cstdint>

// ---------------------------------------------------------------------------
// ConversationalGraph: 2x GraphConv (D=H=64) + leaky_relu + mean-pool + linear
//   layer: out = segsum(x[src]*w -> dst) @ W_rel + b + x @ W_root
// N=100000, E=1250000, 512 graphs, C=8.
// Split architecture (R13) + gather v3: lane-parallel edge fetch + shfl
// broadcast (1 LDG per 32 edges + 1 row LDG per edge), fp16 gather operand,
// fp32 accumulation, f32x2 packed-FMA node GEMM.
// ---------------------------------------------------------------------------

#define NMAX   100000
#define EMAX   1250000
#define DIM    64
#define NGRAPH 512
#define SCANB  1024
#define NBLK   ((NMAX + SCANB - 1) / SCANB)   // 98

__device__ float  g_agg[NMAX * DIM];
__device__ __half g_xh[NMAX * DIM];
__device__ __half g_h1h[NMAX * DIM];
__device__ float  g_pooled[NGRAPH * DIM];
__device__ float  g_counts[NGRAPH];

__device__ alignas(16) int2 g_edges[EMAX];   // (src, w-bits) sorted by dst
__device__ int  g_deg[NMAX];
__device__ int  g_rowstart[NMAX + 1];
__device__ int  g_cursor[NMAX];
__device__ int  g_blocksum[NBLK + 1];

// ---- packed f32x2 helpers --------------------------------------------------
__device__ __forceinline__ uint64_t ffma2(uint64_t a, uint64_t b, uint64_t c) {
    uint64_t d;
    asm("fma.rn.f32x2 %0, %1, %2, %3;" : "=l"(d) : "l"(a), "l"(b), "l"(c));
    return d;
}
__device__ __forceinline__ uint64_t splat2(float f) {
    uint64_t d;
    asm("mov.b64 %0, {%1, %1};" : "=l"(d) : "f"(f));
    return d;
}
__device__ __forceinline__ void unpack2(uint64_t v, float& lo, float& hi) {
    asm("mov.b64 {%0, %1}, %2;" : "=f"(lo), "=f"(hi) : "l"(v));
}

// ---------------------------------------------------------------------------
// prep: zero deg/pooled/counts + convert x(fp32) -> xh(fp16).  Grid covers n2.
// ---------------------------------------------------------------------------
__global__ void prep_kernel(const float* __restrict__ x, __half* __restrict__ xh,
                            int* deg, float* pooled, float* counts,
                            int N, int n2 /* = N*DIM/2 */) {
    int i = blockIdx.x * blockDim.x + threadIdx.x;
    if (i < n2) {
        float2 v = reinterpret_cast<const float2*>(x)[i];
        reinterpret_cast<__half2*>(xh)[i] = __floats2half2_rn(v.x, v.y);
    }
    if (i < N) deg[i] = 0;
    if (i < NGRAPH * DIM) pooled[i] = 0.f;
    if (i < NGRAPH) counts[i] = 0.f;
}

// ---------------------------------------------------------------------------
// CSR build: histogram, scan (block-level + fold), scatter (+graph counts)
// ---------------------------------------------------------------------------
__global__ void hist_kernel(const int* __restrict__ ei, int* __restrict__ deg, int E) {
    int e = blockIdx.x * blockDim.x + threadIdx.x;
    if (e < E) atomicAdd(&deg[__ldg(&ei[e + E])], 1);
}

__global__ void scan1_kernel(const int* __restrict__ deg, int* __restrict__ rowstart,
                             int* __restrict__ blocksum, int N) {
    __shared__ int s[SCANB];
    int i = blockIdx.x * SCANB + threadIdx.x;
    int v = (i < N) ? deg[i] : 0;
    s[threadIdx.x] = v;
    __syncthreads();
#pragma unroll
    for (int off = 1; off < SCANB; off <<= 1) {
        int t = (threadIdx.x >= off) ? s[threadIdx.x - off] : 0;
        __syncthreads();
        s[threadIdx.x] += t;
        __syncthreads();
    }
    if (i < N) rowstart[i] = s[threadIdx.x] - v;   // exclusive within block
    if (threadIdx.x == SCANB - 1) blocksum[blockIdx.x] = s[SCANB - 1];
}

__global__ void scan3_kernel(int* __restrict__ rowstart, int* __restrict__ cursor,
                             const int* __restrict__ blocksum, int N, int E, int nb) {
    __shared__ int s[128];
    const int t = threadIdx.x;
    if (t < 128) {
        s[t] = (t > 0 && t - 1 < nb) ? blocksum[t - 1] : 0;
    }
    __syncthreads();
#pragma unroll
    for (int off = 1; off < 128; off <<= 1) {
        int u = (t < 128 && t >= off) ? s[t - off] : 0;
        __syncthreads();
        if (t < 128) s[t] += u;
        __syncthreads();
    }
    int i = blockIdx.x * blockDim.x + t;
    if (i < N) {
        int r = rowstart[i] + s[i >> 10];
        rowstart[i] = r;
        cursor[i] = r;
    }
    if (i == 0) rowstart[N] = E;
}

__global__ void scatter_kernel(const int* __restrict__ ei, const float* __restrict__ w,
                               int* __restrict__ cursor, int2* __restrict__ edges,
                               const int* __restrict__ batch, float* __restrict__ counts,
                               int E, int N) {
    int e = blockIdx.x * blockDim.x + threadIdx.x;
    if (e >= E) return;
    int s = __ldg(&ei[e]);
    int d = __ldg(&ei[e + E]);
    int pos = atomicAdd(&cursor[d], 1);
    edges[pos] = make_int2(s, __float_as_int(__ldg(&w[e])));
    if (e < N) atomicAdd(&counts[__ldg(&batch[e])], 1.0f);   // fused graph counts
}

// ---------------------------------------------------------------------------
// Gather v3: one warp per node. Edges fetched 32-at-a-time lane-parallel
// (1 LDG per 32 edges), then distributed via shfl — row-load addresses come
// from registers, so only the row LDG remains on the per-edge path. fp16
// rows (128B per edge per warp), fp32 accumulate.
// ---------------------------------------------------------------------------
__global__ void __launch_bounds__(256)
gather_kernel(const __half* __restrict__ xh, const int2* __restrict__ edges,
              const int* __restrict__ rowstart, float* __restrict__ agg, int N) {
    int gtid = blockIdx.x * blockDim.x + threadIdx.x;
    int node = gtid >> 5;
    int lane = gtid & 31;
    if (node >= N) return;
    int beg = __ldg(&rowstart[node]);
    int end = __ldg(&rowstart[node + 1]);
    float a0 = 0.f, a1 = 0.f;

    for (int base = beg; base < end; base += 32) {
        int rem = end - base;
        int cnt = rem < 32 ? rem : 32;
        int2 my = make_int2(0, 0);
        if (lane < cnt) my = __ldg(&edges[base + lane]);

        int j = 0;
        for (; j + 4 <= cnt; j += 4) {
#pragma unroll
            for (int u = 0; u < 4; u++) {
                int   src = __shfl_sync(0xffffffffu, my.x, j + u);
                float wt  = __int_as_float(__shfl_sync(0xffffffffu, my.y, j + u));
                __half2 hv = __ldg(reinterpret_cast<const __half2*>(
                    xh + (size_t)src * DIM) + lane);
                float2 xv = __half22float2(hv);
                a0 += wt * xv.x;
                a1 += wt * xv.y;
            }
        }
        for (; j < cnt; j++) {
            int   src = __shfl_sync(0xffffffffu, my.x, j);
            float wt  = __int_as_float(__shfl_sync(0xffffffffu, my.y, j));
            __half2 hv = __ldg(reinterpret_cast<const __half2*>(
                xh + (size_t)src * DIM) + lane);
            float2 xv = __half22float2(hv);
            a0 += wt * xv.x;
            a1 += wt * xv.y;
        }
    }
    *reinterpret_cast<float2*>(agg + (size_t)node * DIM + lane * 2) =
        make_float2(a0, a1);
}

// ---------------------------------------------------------------------------
// Node kernel: res = leaky( Aagg @ Wrel + Axh @ Wroot + b )
// [N x 128] @ [128 x 64] GEMM via packed fma.rn.f32x2 (8x4 micro-tile).
// pool==0 -> half feature rows (outh); pool==1 -> fp32 atomic pool accum.
// ---------------------------------------------------------------------------
__global__ void __launch_bounds__(256)
node_kernel(const float* __restrict__ Aagg, const __half* __restrict__ Axh,
            const float* __restrict__ Wrel, const float* __restrict__ Wroot,
            const float* __restrict__ bias,
            __half* __restrict__ outh,
            const int* __restrict__ batch,
            float* __restrict__ pooled,
            int N, int pool) {
    __shared__ float As[16][136];   // [k][row], 128 rows + pad
    __shared__ float Ws[16][64];    // [k][col]

    const int tid = threadIdx.x;
    const int tx = tid & 15;        // col group: cols tx*4 .. +3
    const int ty = tid >> 4;        // row group: rows ty*8 .. +7
    const int rowBase = blockIdx.x * 128;

    const int lr  = tid >> 1;          // A row 0..127
    const int lks = (tid & 1) * 8;     // k offset {0,8}
    const int wk = tid >> 4;
    const int wj = (tid & 15) * 4;

    uint64_t accp[4][4];            // [row-pair][col]
#pragma unroll
    for (int p = 0; p < 4; p++)
#pragma unroll
        for (int c = 0; c < 4; c++) accp[p][c] = 0ull;

#pragma unroll
    for (int kc = 0; kc < 8; kc++) {
        const int kk = (kc & 3) * 16;
        const float* Wsrc = (kc < 4) ? Wrel : Wroot;

        const int arow = rowBase + lr;
        float4 av0 = make_float4(0.f, 0.f, 0.f, 0.f);
        float4 av1 = av0;
        if (arow < N) {
            if (kc < 4) {
                const float* base = Aagg + (size_t)arow * DIM + kk + lks;
                av0 = *reinterpret_cast<const float4*>(base);
                av1 = *reinterpret_cast<const float4*>(base + 4);
            } else {
                const __half2* base = reinterpret_cast<const __half2*>(
                    Axh + (size_t)arow * DIM + kk + lks);
                __half2 h[4];
                *reinterpret_cast<uint4*>(h) =
                    *reinterpret_cast<const uint4*>(base);   // 8 halves
                float2 f0 = __half22float2(h[0]);
                float2 f1 = __half22float2(h[1]);
                float2 f2 = __half22float2(h[2]);
                float2 f3 = __half22float2(h[3]);
                av0 = make_float4(f0.x, f0.y, f1.x, f1.y);
                av1 = make_float4(f2.x, f2.y, f3.x, f3.y);
            }
        }
        float4 wv = *reinterpret_cast<const float4*>(Wsrc + (wk + kk) * DIM + wj);

        __syncthreads();
        As[lks + 0][lr] = av0.x;
        As[lks + 1][lr] = av0.y;
        As[lks + 2][lr] = av0.z;
        As[lks + 3][lr] = av0.w;
        As[lks + 4][lr] = av1.x;
        As[lks + 5][lr] = av1.y;
        As[lks + 6][lr] = av1.z;
        As[lks + 7][lr] = av1.w;
        *reinterpret_cast<float4*>(&Ws[wk][wj]) = wv;
        __syncthreads();

#pragma unroll
        for (int k = 0; k < 16; k++) {
            const uint64_t* arow2 =
                reinterpret_cast<const uint64_t*>(&As[k][ty * 8]);
            uint64_t ap0 = arow2[0];
            uint64_t ap1 = arow2[1];
            uint64_t ap2 = arow2[2];
            uint64_t ap3 = arow2[3];
            float4 wq = *reinterpret_cast<float4*>(&Ws[k][tx * 4]);
            uint64_t w0 = splat2(wq.x);
            uint64_t w1 = splat2(wq.y);
            uint64_t w2 = splat2(wq.z);
            uint64_t w3 = splat2(wq.w);
            accp[0][0] = ffma2(ap0, w0, accp[0][0]);
            accp[0][1] = ffma2(ap0, w1, accp[0][1]);
            accp[0][2] = ffma2(ap0, w2, accp[0][2]);
            accp[0][3] = ffma2(ap0, w3, accp[0][3]);
            accp[1][0] = ffma2(ap1, w0, accp[1][0]);
            accp[1][1] = ffma2(ap1, w1, accp[1][1]);
            accp[1][2] = ffma2(ap1, w2, accp[1][2]);
            accp[1][3] = ffma2(ap1, w3, accp[1][3]);
            accp[2][0] = ffma2(ap2, w0, accp[2][0]);
            accp[2][1] = ffma2(ap2, w1, accp[2][1]);
            accp[2][2] = ffma2(ap2, w2, accp[2][2]);
            accp[2][3] = ffma2(ap2, w3, accp[2][3]);
            accp[3][0] = ffma2(ap3, w0, accp[3][0]);
            accp[3][1] = ffma2(ap3, w1, accp[3][1]);
            accp[3][2] = ffma2(ap3, w2, accp[3][2]);
            accp[3][3] = ffma2(ap3, w3, accp[3][3]);
        }
    }

    const float4 b4 = *reinterpret_cast<const float4*>(bias + tx * 4);
#pragma unroll
    for (int p = 0; p < 4; p++) {
        float lo[4], hi[4];
#pragma unroll
        for (int c = 0; c < 4; c++) unpack2(accp[p][c], lo[c], hi[c]);

#pragma unroll
        for (int h = 0; h < 2; h++) {
            const int r = rowBase + ty * 8 + 2 * p + h;
            if (r >= N) continue;
            const float* src = h ? hi : lo;
            float v0 = src[0] + b4.x;
            float v1 = src[1] + b4.y;
            float v2 = src[2] + b4.z;
            float v3 = src[3] + b4.w;
            v0 = (v0 > 0.f) ? v0 : 0.01f * v0;
            v1 = (v1 > 0.f) ? v1 : 0.01f * v1;
            v2 = (v2 > 0.f) ? v2 : 0.01f * v2;
            v3 = (v3 > 0.f) ? v3 : 0.01f * v3;
            if (!pool) {
                __half2 h01 = __floats2half2_rn(v0, v1);
                __half2 h23 = __floats2half2_rn(v2, v3);
                uint2 packed = make_uint2(
                    *reinterpret_cast<uint32_t*>(&h01),
                    *reinterpret_cast<uint32_t*>(&h23));
                *reinterpret_cast<uint2*>(outh + (size_t)r * DIM + tx * 4) = packed;
            } else {
                int g = batch[r];
                float4 v = make_float4(v0, v1, v2, v3);
                atomicAdd(reinterpret_cast<float4*>(pooled + (size_t)g * DIM + tx * 4), v);
            }
        }
    }
}

// ---------------------------------------------------------------------------
__global__ void final_kernel(const float* __restrict__ pooled,
                             const float* __restrict__ counts,
                             const float* __restrict__ Wl,
                             const float* __restrict__ bl,
                             float* __restrict__ out) {
    int g = blockIdx.x * blockDim.x + threadIdx.x;
    if (g >= NGRAPH) return;
    float inv = 1.0f / fmaxf(counts[g], 1.0f);
    float acc[8];
#pragma unroll
    for (int c = 0; c < 8; c++) acc[c] = 0.f;
    for (int d = 0; d < DIM; d++) {
        float p = pooled[g * DIM + d];
#pragma unroll
        for (int c = 0; c < 8; c++) acc[c] += p * Wl[d * 8 + c];
    }
#pragma unroll
    for (int c = 0; c < 8; c++) out[g * 8 + c] = bl[c] + inv * acc[c];
}

// ---------------------------------------------------------------------------
extern "C" void kernel_launch(void* const* d_in, const int* in_sizes, int n_in,
                              void* d_out, int out_size) {
    const float* x      = (const float*)d_in[0];
    const int*   ei     = (const int*)d_in[1];
    const float* w      = (const float*)d_in[2];
    const int*   batch  = (const int*)d_in[3];
    const float* W1root = (const float*)d_in[4];
    const float* W1rel  = (const float*)d_in[5];
    const float* b1     = (const float*)d_in[6];
    const float* W2root = (const float*)d_in[7];
    const float* W2rel  = (const float*)d_in[8];
    const float* b2     = (const float*)d_in[9];
    const float* Wl     = (const float*)d_in[10];
    const float* bl     = (const float*)d_in[11];
    float* out = (float*)d_out;

    const int N = in_sizes[0] / DIM;
    const int E = in_sizes[2];

    float *agg, *pooled, *counts;
    __half *xh, *h1h;
    int2* edges; int *deg, *rowstart, *cursor, *blocksum;
    cudaGetSymbolAddress((void**)&agg,      g_agg);
    cudaGetSymbolAddress((void**)&xh,       g_xh);
    cudaGetSymbolAddress((void**)&h1h,      g_h1h);
    cudaGetSymbolAddress((void**)&pooled,   g_pooled);
    cudaGetSymbolAddress((void**)&counts,   g_counts);
    cudaGetSymbolAddress((void**)&edges,    g_edges);
    cudaGetSymbolAddress((void**)&deg,      g_deg);
    cudaGetSymbolAddress((void**)&rowstart, g_rowstart);
    cudaGetSymbolAddress((void**)&cursor,   g_cursor);
    cudaGetSymbolAddress((void**)&blocksum, g_blocksum);

    const int nb = (N + SCANB - 1) / SCANB;
    const int n2 = N * DIM / 2;

    // ---- prep (zero + fp16 convert) + CSR build ----
    prep_kernel<<<(n2 + 255) / 256, 256>>>(x, xh, deg, pooled, counts, N, n2);
    hist_kernel<<<(E + 255) / 256, 256>>>(ei, deg, E);
    scan1_kernel<<<nb, SCANB>>>(deg, rowstart, blocksum, N);
    scan3_kernel<<<(N + 255) / 256, 256>>>(rowstart, cursor, blocksum, N, E, nb);
    scatter_kernel<<<(E + 255) / 256, 256>>>(ei, w, cursor, edges, batch, counts, E, N);

    const int gatherBlocks = (N * 32 + 255) / 256;
    const int nodeBlocks = (N + 127) / 128;

    // ---- Layer 1 ----
    gather_kernel<<<gatherBlocks, 256>>>(xh, edges, rowstart, agg, N);
    node_kernel<<<nodeBlocks, 256>>>(agg, xh, W1rel, W1root, b1,
                                     h1h, nullptr, nullptr, N, 0);
    // ---- Layer 2 (pool fused into epilogue) ----
    gather_kernel<<<gatherBlocks, 256>>>(h1h, edges, rowstart, agg, N);
    node_kernel<<<nodeBlocks, 256>>>(agg, h1h, W2rel, W2root, b2,
                                     nullptr, batch, pooled, N, 1);

    final_kernel<<<(NGRAPH + 255) / 256, 256>>>(pooled, counts, Wl, bl, out);
}

// round 16
// speedup vs baseline: 1.7967x; 1.3834x over previous
#include <cuda_runtime.h>
#include <cuda_fp16.h>
#include <cstdint>

// ---------------------------------------------------------------------------
// ConversationalGraph: 2x GraphConv (D=H=64) + leaky_relu + mean-pool + linear
//   layer: out = segsum(x[src]*w -> dst) @ W_rel + b + x @ W_root
// N=100000, E=1250000, 512 graphs, C=8.
// CSR counting-sort + warp gather (fp16 in/out, fp32 accum) +
// TENSOR-CORE node GEMM (mma.sync.m16n8k16 f16->f32, HMMA).
// ---------------------------------------------------------------------------

#define NMAX   100000
#define EMAX   1250000
#define DIM    64
#define NGRAPH 512
#define SCANB  1024
#define NBLK   ((NMAX + SCANB - 1) / SCANB)   // 98

__device__ __half g_aggh[NMAX * DIM];
__device__ __half g_xh[NMAX * DIM];
__device__ __half g_h1h[NMAX * DIM];
__device__ __half g_wcat1[128 * DIM];   // rows 0-63: W1rel, 64-127: W1root
__device__ __half g_wcat2[128 * DIM];
__device__ float  g_pooled[NGRAPH * DIM];
__device__ float  g_counts[NGRAPH];

__device__ alignas(16) int2 g_edges[EMAX];   // (src, w-bits) sorted by dst
__device__ int  g_deg[NMAX];
__device__ int  g_rowstart[NMAX + 1];
__device__ int  g_cursor[NMAX];
__device__ int  g_blocksum[NBLK + 1];

// ---------------------------------------------------------------------------
// prep: zero deg/pooled/counts, convert x -> fp16, build fp16 Wcat matrices
// ---------------------------------------------------------------------------
__global__ void prep_kernel(const float* __restrict__ x, __half* __restrict__ xh,
                            const float* __restrict__ W1rel, const float* __restrict__ W1root,
                            const float* __restrict__ W2rel, const float* __restrict__ W2root,
                            __half* __restrict__ wcat1, __half* __restrict__ wcat2,
                            int* deg, float* pooled, float* counts,
                            int N, int n2 /* = N*DIM/2 */) {
    int i = blockIdx.x * blockDim.x + threadIdx.x;
    if (i < n2) {
        float2 v = reinterpret_cast<const float2*>(x)[i];
        reinterpret_cast<__half2*>(xh)[i] = __floats2half2_rn(v.x, v.y);
    }
    if (i < 128 * DIM) {
        int k = i >> 6, n = i & 63;
        float w1 = (k < 64) ? W1rel[k * DIM + n] : W1root[(k - 64) * DIM + n];
        float w2 = (k < 64) ? W2rel[k * DIM + n] : W2root[(k - 64) * DIM + n];
        wcat1[i] = __float2half_rn(w1);
        wcat2[i] = __float2half_rn(w2);
    }
    if (i < N) deg[i] = 0;
    if (i < NGRAPH * DIM) pooled[i] = 0.f;
    if (i < NGRAPH) counts[i] = 0.f;
}

// ---------------------------------------------------------------------------
// CSR build: histogram, scan (block-level + fold), scatter (+graph counts)
// ---------------------------------------------------------------------------
__global__ void hist_kernel(const int* __restrict__ ei, int* __restrict__ deg, int E) {
    int e = blockIdx.x * blockDim.x + threadIdx.x;
    if (e < E) atomicAdd(&deg[__ldg(&ei[e + E])], 1);
}

__global__ void scan1_kernel(const int* __restrict__ deg, int* __restrict__ rowstart,
                             int* __restrict__ blocksum, int N) {
    __shared__ int s[SCANB];
    int i = blockIdx.x * SCANB + threadIdx.x;
    int v = (i < N) ? deg[i] : 0;
    s[threadIdx.x] = v;
    __syncthreads();
#pragma unroll
    for (int off = 1; off < SCANB; off <<= 1) {
        int t = (threadIdx.x >= off) ? s[threadIdx.x - off] : 0;
        __syncthreads();
        s[threadIdx.x] += t;
        __syncthreads();
    }
    if (i < N) rowstart[i] = s[threadIdx.x] - v;   // exclusive within block
    if (threadIdx.x == SCANB - 1) blocksum[blockIdx.x] = s[SCANB - 1];
}

__global__ void scan3_kernel(int* __restrict__ rowstart, int* __restrict__ cursor,
                             const int* __restrict__ blocksum, int N, int E, int nb) {
    __shared__ int s[128];
    const int t = threadIdx.x;
    if (t < 128) {
        s[t] = (t > 0 && t - 1 < nb) ? blocksum[t - 1] : 0;
    }
    __syncthreads();
#pragma unroll
    for (int off = 1; off < 128; off <<= 1) {
        int u = (t < 128 && t >= off) ? s[t - off] : 0;
        __syncthreads();
        if (t < 128) s[t] += u;
        __syncthreads();
    }
    int i = blockIdx.x * blockDim.x + t;
    if (i < N) {
        int r = rowstart[i] + s[i >> 10];
        rowstart[i] = r;
        cursor[i] = r;
    }
    if (i == 0) rowstart[N] = E;
}

__global__ void scatter_kernel(const int* __restrict__ ei, const float* __restrict__ w,
                               int* __restrict__ cursor, int2* __restrict__ edges,
                               const int* __restrict__ batch, float* __restrict__ counts,
                               int E, int N) {
    int e = blockIdx.x * blockDim.x + threadIdx.x;
    if (e >= E) return;
    int s = __ldg(&ei[e]);
    int d = __ldg(&ei[e + E]);
    int pos = atomicAdd(&cursor[d], 1);
    edges[pos] = make_int2(s, __float_as_int(__ldg(&w[e])));
    if (e < N) atomicAdd(&counts[__ldg(&batch[e])], 1.0f);   // fused graph counts
}

// ---------------------------------------------------------------------------
// Gather (R13 form): one warp per node; lane covers cols {2l, 2l+1} via one
// half2 load per edge. fp32 accumulate, fp16 store.
// ---------------------------------------------------------------------------
__global__ void __launch_bounds__(256)
gather_kernel(const __half* __restrict__ xh, const int2* __restrict__ edges,
              const int* __restrict__ rowstart, __half* __restrict__ aggh, int N) {
    int gtid = blockIdx.x * blockDim.x + threadIdx.x;
    int node = gtid >> 5;
    int lane = gtid & 31;
    if (node >= N) return;
    int beg = __ldg(&rowstart[node]);
    int end = __ldg(&rowstart[node + 1]);
    float a0 = 0.f, a1 = 0.f;
#pragma unroll 4
    for (int i = beg; i < end; i++) {
        int2 ed = __ldg(&edges[i]);                 // broadcast across warp
        float wt = __int_as_float(ed.y);
        __half2 hv = __ldg(reinterpret_cast<const __half2*>(
            xh + (size_t)ed.x * DIM) + lane);
        float2 xv = __half22float2(hv);
        a0 += wt * xv.x;
        a1 += wt * xv.y;
    }
    reinterpret_cast<__half2*>(aggh + (size_t)node * DIM)[lane] =
        __floats2half2_rn(a0, a1);
}

// ---------------------------------------------------------------------------
// Tensor-core node kernel:
//   res = leaky( [aggh | feath] @ Wcat + b ),  all operands fp16, accum fp32.
// Block: 128 rows x 64 cols, 8 warps (warp w -> rows w*16..+15).
// Two K-phases (agg rows, feat rows); per phase stage A[128x64] and W[64x64]
// fp16 in smem (stride 72 halves -> conflict-free ldmatrix), then
// ldmatrix.x4 (A) / ldmatrix.x4.trans (B) + mma.sync.m16n8k16.
// Epilogue through smem C (fp32, aliases A/B region).
// pool==0 -> half rows to outh; pool==1 -> float4 atomic pool accumulation.
// ---------------------------------------------------------------------------
#define AS 72          // A smem stride (halves)
#define BS 72          // B smem stride (halves)
#define CSair 72       // C smem stride (floats)

__global__ void __launch_bounds__(256)
node_kernel(const __half* __restrict__ aggh, const __half* __restrict__ feath,
            const __half* __restrict__ wcat,
            const float* __restrict__ bias,
            __half* __restrict__ outh,
            const int* __restrict__ batch,
            float* __restrict__ pooled,
            int N, int pool) {
    __shared__ __align__(16) char smem[128 * CSair * 4];   // 36864 B union
    __half* Ash = reinterpret_cast<__half*>(smem);                    // [128][AS]
    __half* Bsh = reinterpret_cast<__half*>(smem + 128 * AS * 2);     // [64][BS]
    float*  Cs  = reinterpret_cast<float*>(smem);                     // [128][CSair]

    const int tid  = threadIdx.x;
    const int warp = tid >> 5;
    const int lane = tid & 31;
    const int rowBase = blockIdx.x * 128;

    float acc[8][4];
#pragma unroll
    for (int nt = 0; nt < 8; nt++)
#pragma unroll
        for (int i = 0; i < 4; i++) acc[nt][i] = 0.f;

    // fill indices: thread t loads 8 halves (uint4) per iter
    const int fr = tid >> 3;          // 0..31
    const int fc = (tid & 7) * 8;     // 0,8,..,56

    // ldmatrix lane addressing (same pattern for A and B-trans)
    const int lrow  = lane & 15;
    const int lhalf = (lane >> 4) << 3;

#pragma unroll
    for (int phase = 0; phase < 2; phase++) {
        const __half* Asrc = phase ? feath : aggh;
        __syncthreads();   // previous phase's reads done before refill
        // stage A: 128 rows x 64 halves
#pragma unroll
        for (int it = 0; it < 4; it++) {
            int r = fr + it * 32;
            int gr = rowBase + r;
            uint4 v = make_uint4(0u, 0u, 0u, 0u);
            if (gr < N)
                v = *reinterpret_cast<const uint4*>(Asrc + (size_t)gr * DIM + fc);
            *reinterpret_cast<uint4*>(Ash + r * AS + fc) = v;
        }
        // stage B: 64 rows x 64 halves from wcat rows [phase*64, +64)
#pragma unroll
        for (int it = 0; it < 2; it++) {
            int r = fr + it * 32;
            uint4 v = *reinterpret_cast<const uint4*>(
                wcat + (phase * 64 + r) * DIM + fc);
            *reinterpret_cast<uint4*>(Bsh + r * BS + fc) = v;
        }
        __syncthreads();

#pragma unroll
        for (int ks = 0; ks < 4; ks++) {
            const int kb = ks * 16;
            uint32_t a0, a1, a2, a3;
            {
                uint32_t addr = (uint32_t)__cvta_generic_to_shared(
                    Ash + (warp * 16 + lrow) * AS + kb + lhalf);
                asm volatile(
                    "ldmatrix.sync.aligned.m8n8.x4.shared.b16 {%0,%1,%2,%3}, [%4];"
                    : "=r"(a0), "=r"(a1), "=r"(a2), "=r"(a3) : "r"(addr));
            }
#pragma unroll
            for (int nb = 0; nb < 4; nb++) {
                uint32_t b0, b1, b2, b3;
                uint32_t addr = (uint32_t)__cvta_generic_to_shared(
                    Bsh + (kb + lrow) * BS + nb * 16 + lhalf);
                asm volatile(
                    "ldmatrix.sync.aligned.m8n8.x4.trans.shared.b16 {%0,%1,%2,%3}, [%4];"
                    : "=r"(b0), "=r"(b1), "=r"(b2), "=r"(b3) : "r"(addr));
                asm volatile(
                    "mma.sync.aligned.m16n8k16.row.col.f32.f16.f16.f32 "
                    "{%0,%1,%2,%3}, {%4,%5,%6,%7}, {%8,%9}, {%0,%1,%2,%3};"
                    : "+f"(acc[2 * nb][0]), "+f"(acc[2 * nb][1]),
                      "+f"(acc[2 * nb][2]), "+f"(acc[2 * nb][3])
                    : "r"(a0), "r"(a1), "r"(a2), "r"(a3), "r"(b0), "r"(b1));
                asm volatile(
                    "mma.sync.aligned.m16n8k16.row.col.f32.f16.f16.f32 "
                    "{%0,%1,%2,%3}, {%4,%5,%6,%7}, {%8,%9}, {%0,%1,%2,%3};"
                    : "+f"(acc[2 * nb + 1][0]), "+f"(acc[2 * nb + 1][1]),
                      "+f"(acc[2 * nb + 1][2]), "+f"(acc[2 * nb + 1][3])
                    : "r"(a0), "r"(a1), "r"(a2), "r"(a3), "r"(b2), "r"(b3));
            }
        }
    }
    __syncthreads();   // all smem reads done; C aliases A/B

    // write fragments to Cs
    {
        const int qrow = warp * 16 + (lane >> 2);
        const int qcol = (lane & 3) * 2;
#pragma unroll
        for (int nt = 0; nt < 8; nt++) {
            *reinterpret_cast<float2*>(&Cs[qrow * CSair + nt * 8 + qcol]) =
                make_float2(acc[nt][0], acc[nt][1]);
            *reinterpret_cast<float2*>(&Cs[(qrow + 8) * CSair + nt * 8 + qcol]) =
                make_float2(acc[nt][2], acc[nt][3]);
        }
    }
    __syncthreads();

    // epilogue: bias + leaky + store/pool
    const int tx = tid & 15;        // col group (4 cols)
    const int ty = tid >> 4;        // row block (8 rows)
    const float4 b4 = *reinterpret_cast<const float4*>(bias + tx * 4);
#pragma unroll
    for (int rr = 0; rr < 8; rr++) {
        const int rl = ty * 8 + rr;
        const int r = rowBase + rl;
        if (r >= N) continue;
        float4 v = *reinterpret_cast<float4*>(&Cs[rl * CSair + tx * 4]);
        v.x += b4.x; v.y += b4.y; v.z += b4.z; v.w += b4.w;
        v.x = (v.x > 0.f) ? v.x : 0.01f * v.x;
        v.y = (v.y > 0.f) ? v.y : 0.01f * v.y;
        v.z = (v.z > 0.f) ? v.z : 0.01f * v.z;
        v.w = (v.w > 0.f) ? v.w : 0.01f * v.w;
        if (!pool) {
            __half2 h01 = __floats2half2_rn(v.x, v.y);
            __half2 h23 = __floats2half2_rn(v.z, v.w);
            uint2 packed = make_uint2(*reinterpret_cast<uint32_t*>(&h01),
                                      *reinterpret_cast<uint32_t*>(&h23));
            *reinterpret_cast<uint2*>(outh + (size_t)r * DIM + tx * 4) = packed;
        } else {
            int g = batch[r];
            atomicAdd(reinterpret_cast<float4*>(pooled + (size_t)g * DIM + tx * 4), v);
        }
    }
}

// ---------------------------------------------------------------------------
__global__ void final_kernel(const float* __restrict__ pooled,
                             const float* __restrict__ counts,
                             const float* __restrict__ Wl,
                             const float* __restrict__ bl,
                             float* __restrict__ out) {
    int g = blockIdx.x * blockDim.x + threadIdx.x;
    if (g >= NGRAPH) return;
    float inv = 1.0f / fmaxf(counts[g], 1.0f);
    float acc[8];
#pragma unroll
    for (int c = 0; c < 8; c++) acc[c] = 0.f;
    for (int d = 0; d < DIM; d++) {
        float p = pooled[g * DIM + d];
#pragma unroll
        for (int c = 0; c < 8; c++) acc[c] += p * Wl[d * 8 + c];
    }
#pragma unroll
    for (int c = 0; c < 8; c++) out[g * 8 + c] = bl[c] + inv * acc[c];
}

// ---------------------------------------------------------------------------
extern "C" void kernel_launch(void* const* d_in, const int* in_sizes, int n_in,
                              void* d_out, int out_size) {
    const float* x      = (const float*)d_in[0];
    const int*   ei     = (const int*)d_in[1];
    const float* w      = (const float*)d_in[2];
    const int*   batch  = (const int*)d_in[3];
    const float* W1root = (const float*)d_in[4];
    const float* W1rel  = (const float*)d_in[5];
    const float* b1     = (const float*)d_in[6];
    const float* W2root = (const float*)d_in[7];
    const float* W2rel  = (const float*)d_in[8];
    const float* b2     = (const float*)d_in[9];
    const float* Wl     = (const float*)d_in[10];
    const float* bl     = (const float*)d_in[11];
    float* out = (float*)d_out;

    const int N = in_sizes[0] / DIM;
    const int E = in_sizes[2];

    float *pooled, *counts;
    __half *aggh, *xh, *h1h, *wcat1, *wcat2;
    int2* edges; int *deg, *rowstart, *cursor, *blocksum;
    cudaGetSymbolAddress((void**)&aggh,     g_aggh);
    cudaGetSymbolAddress((void**)&xh,       g_xh);
    cudaGetSymbolAddress((void**)&h1h,      g_h1h);
    cudaGetSymbolAddress((void**)&wcat1,    g_wcat1);
    cudaGetSymbolAddress((void**)&wcat2,    g_wcat2);
    cudaGetSymbolAddress((void**)&pooled,   g_pooled);
    cudaGetSymbolAddress((void**)&counts,   g_counts);
    cudaGetSymbolAddress((void**)&edges,    g_edges);
    cudaGetSymbolAddress((void**)&deg,      g_deg);
    cudaGetSymbolAddress((void**)&rowstart, g_rowstart);
    cudaGetSymbolAddress((void**)&cursor,   g_cursor);
    cudaGetSymbolAddress((void**)&blocksum, g_blocksum);

    const int nb = (N + SCANB - 1) / SCANB;
    const int n2 = N * DIM / 2;

    // ---- prep (zero + fp16 conversions) + CSR build ----
    prep_kernel<<<(n2 + 255) / 256, 256>>>(x, xh, W1rel, W1root, W2rel, W2root,
                                           wcat1, wcat2, deg, pooled, counts, N, n2);
    hist_kernel<<<(E + 255) / 256, 256>>>(ei, deg, E);
    scan1_kernel<<<nb, SCANB>>>(deg, rowstart, blocksum, N);
    scan3_kernel<<<(N + 255) / 256, 256>>>(rowstart, cursor, blocksum, N, E, nb);
    scatter_kernel<<<(E + 255) / 256, 256>>>(ei, w, cursor, edges, batch, counts, E, N);

    const int gatherBlocks = (N * 32 + 255) / 256;
    const int nodeBlocks = (N + 127) / 128;

    // ---- Layer 1 ----
    gather_kernel<<<gatherBlocks, 256>>>(xh, edges, rowstart, aggh, N);
    node_kernel<<<nodeBlocks, 256>>>(aggh, xh, wcat1, b1,
                                     h1h, nullptr, nullptr, N, 0);
    // ---- Layer 2 (pool fused into epilogue) ----
    gather_kernel<<<gatherBlocks, 256>>>(h1h, edges, rowstart, aggh, N);
    node_kernel<<<nodeBlocks, 256>>>(aggh, h1h, wcat2, b2,
                                     nullptr, batch, pooled, N, 1);

    final_kernel<<<(NGRAPH + 255) / 256, 256>>>(pooled, counts, Wl, bl, out);
}

// round 17
// speedup vs baseline: 1.8731x; 1.0425x over previous
#include <cuda_runtime.h>
#include <cuda_fp16.h>
#include <cstdint>

// ---------------------------------------------------------------------------
// ConversationalGraph: 2x GraphConv (D=H=64) + leaky_relu + mean-pool + linear
// N=100000, E=1250000, 512 graphs, C=8.
// CSR counting-sort (fused: prep+hist, single-pass lookback scan) +
// warp gather (fp16 in/out, fp32 accum) + tensor-core node GEMM (HMMA).
// deg is re-zeroed by final_kernel each call (zero-invariant across calls).
// ---------------------------------------------------------------------------

#define NMAX   100000
#define EMAX   1250000
#define DIM    64
#define NGRAPH 512
#define SCANB  1024
#define NBLK   ((NMAX + SCANB - 1) / SCANB)   // 98

__device__ __half g_aggh[NMAX * DIM];
__device__ __half g_xh[NMAX * DIM];
__device__ __half g_h1h[NMAX * DIM];
__device__ __half g_wcat1[128 * DIM];   // rows 0-63: W1rel, 64-127: W1root
__device__ __half g_wcat2[128 * DIM];
__device__ float  g_pooled[NGRAPH * DIM];
__device__ float  g_counts[NGRAPH];

__device__ alignas(16) int2 g_edges[EMAX];   // (src, w-bits) sorted by dst
__device__ int  g_deg[NMAX];                 // zeroed by final_kernel (invariant)
__device__ int  g_rowstart[NMAX + 1];
__device__ int  g_cursor[NMAX];
__device__ unsigned long long g_pub[NBLK];   // lookback publications

// ---------------------------------------------------------------------------
// prep: convert x -> fp16, build fp16 Wcat, HISTOGRAM dst degrees (deg==0 on
// entry by invariant), zero pooled/counts/pub.
// ---------------------------------------------------------------------------
__global__ void prep_kernel(const float* __restrict__ x, __half* __restrict__ xh,
                            const float* __restrict__ W1rel, const float* __restrict__ W1root,
                            const float* __restrict__ W2rel, const float* __restrict__ W2root,
                            __half* __restrict__ wcat1, __half* __restrict__ wcat2,
                            const int* __restrict__ ei, int* __restrict__ deg,
                            float* pooled, float* counts, unsigned long long* pub,
                            int N, int E, int n2 /* = N*DIM/2 */) {
    int i = blockIdx.x * blockDim.x + threadIdx.x;
    if (i < n2) {
        float2 v = reinterpret_cast<const float2*>(x)[i];
        reinterpret_cast<__half2*>(xh)[i] = __floats2half2_rn(v.x, v.y);
    }
    if (i < 128 * DIM) {
        int k = i >> 6, n = i & 63;
        float w1 = (k < 64) ? W1rel[k * DIM + n] : W1root[(k - 64) * DIM + n];
        float w2 = (k < 64) ? W2rel[k * DIM + n] : W2root[(k - 64) * DIM + n];
        wcat1[i] = __float2half_rn(w1);
        wcat2[i] = __float2half_rn(w2);
    }
    if (i < E) atomicAdd(&deg[__ldg(&ei[i + E])], 1);   // fused histogram
    if (i < NGRAPH * DIM) pooled[i] = 0.f;
    if (i < NGRAPH) counts[i] = 0.f;
    if (i < NBLK) pub[i] = 0ull;
}

// ---------------------------------------------------------------------------
// Single-pass exclusive scan of deg -> rowstart/cursor (decoupled lookback).
// 98 blocks of 1024, all co-resident. Publication = (1<<32) | block_total in
// ONE 64-bit word (no fence needed). Threads tid<b spin on predecessor
// aggregates in parallel, block-reduce via shared atomic.
// ---------------------------------------------------------------------------
__global__ void __launch_bounds__(SCANB)
scan_kernel(const int* __restrict__ deg, int* __restrict__ rowstart,
            int* __restrict__ cursor, volatile unsigned long long* pub,
            int N, int E) {
    __shared__ int s[SCANB];
    __shared__ int sprev;
    const int tid = threadIdx.x;
    const int b = blockIdx.x;
    const int i = b * SCANB + tid;
    int v = (i < N) ? deg[i] : 0;
    s[tid] = v;
    __syncthreads();
#pragma unroll
    for (int off = 1; off < SCANB; off <<= 1) {
        int t = (tid >= off) ? s[tid - off] : 0;
        __syncthreads();
        s[tid] += t;
        __syncthreads();
    }
    const int incl = s[tid];
    if (tid == 0) sprev = 0;
    __syncthreads();
    if (tid == 0) {
        unsigned long long total = (unsigned int)s[SCANB - 1];
        atomicExch((unsigned long long*)&pub[b], (1ull << 32) | total);
    }
    if (tid < b) {   // parallel lookback over predecessor aggregates
        unsigned long long p;
        do { p = pub[tid]; } while ((p >> 32) == 0ull);
        atomicAdd(&sprev, (int)(p & 0xffffffffu));
    }
    __syncthreads();
    const int ex = sprev + incl - v;   // exclusive global prefix
    if (i < N) { rowstart[i] = ex; cursor[i] = ex; }
    if (i == 0) rowstart[N] = E;
}

// ---------------------------------------------------------------------------
__global__ void scatter_kernel(const int* __restrict__ ei, const float* __restrict__ w,
                               int* __restrict__ cursor, int2* __restrict__ edges,
                               const int* __restrict__ batch, float* __restrict__ counts,
                               int E, int N) {
    int e = blockIdx.x * blockDim.x + threadIdx.x;
    if (e >= E) return;
    int s = __ldg(&ei[e]);
    int d = __ldg(&ei[e + E]);
    int pos = atomicAdd(&cursor[d], 1);
    edges[pos] = make_int2(s, __float_as_int(__ldg(&w[e])));
    if (e < N) atomicAdd(&counts[__ldg(&batch[e])], 1.0f);   // fused graph counts
}

// ---------------------------------------------------------------------------
// Gather: one warp per node; lane covers cols {2l, 2l+1} via one half2 load
// per edge. fp32 accumulate, fp16 store. (Unchanged from R16.)
// ---------------------------------------------------------------------------
__global__ void __launch_bounds__(256)
gather_kernel(const __half* __restrict__ xh, const int2* __restrict__ edges,
              const int* __restrict__ rowstart, __half* __restrict__ aggh, int N) {
    int gtid = blockIdx.x * blockDim.x + threadIdx.x;
    int node = gtid >> 5;
    int lane = gtid & 31;
    if (node >= N) return;
    int beg = __ldg(&rowstart[node]);
    int end = __ldg(&rowstart[node + 1]);
    float a0 = 0.f, a1 = 0.f;
#pragma unroll 4
    for (int i = beg; i < end; i++) {
        int2 ed = __ldg(&edges[i]);                 // broadcast across warp
        float wt = __int_as_float(ed.y);
        __half2 hv = __ldg(reinterpret_cast<const __half2*>(
            xh + (size_t)ed.x * DIM) + lane);
        float2 xv = __half22float2(hv);
        a0 += wt * xv.x;
        a1 += wt * xv.y;
    }
    reinterpret_cast<__half2*>(aggh + (size_t)node * DIM)[lane] =
        __floats2half2_rn(a0, a1);
}

// ---------------------------------------------------------------------------
// Tensor-core node kernel (unchanged from R16):
//   res = leaky( [aggh | feath] @ Wcat + b ), fp16 operands, fp32 accum.
// ---------------------------------------------------------------------------
#define AS 72
#define BS 72
#define CSair 72

__global__ void __launch_bounds__(256)
node_kernel(const __half* __restrict__ aggh, const __half* __restrict__ feath,
            const __half* __restrict__ wcat,
            const float* __restrict__ bias,
            __half* __restrict__ outh,
            const int* __restrict__ batch,
            float* __restrict__ pooled,
            int N, int pool) {
    __shared__ __align__(16) char smem[128 * CSair * 4];
    __half* Ash = reinterpret_cast<__half*>(smem);                    // [128][AS]
    __half* Bsh = reinterpret_cast<__half*>(smem + 128 * AS * 2);     // [64][BS]
    float*  Cs  = reinterpret_cast<float*>(smem);                     // [128][CSair]

    const int tid  = threadIdx.x;
    const int warp = tid >> 5;
    const int lane = tid & 31;
    const int rowBase = blockIdx.x * 128;

    float acc[8][4];
#pragma unroll
    for (int nt = 0; nt < 8; nt++)
#pragma unroll
        for (int i = 0; i < 4; i++) acc[nt][i] = 0.f;

    const int fr = tid >> 3;
    const int fc = (tid & 7) * 8;
    const int lrow  = lane & 15;
    const int lhalf = (lane >> 4) << 3;

#pragma unroll
    for (int phase = 0; phase < 2; phase++) {
        const __half* Asrc = phase ? feath : aggh;
        __syncthreads();
#pragma unroll
        for (int it = 0; it < 4; it++) {
            int r = fr + it * 32;
            int gr = rowBase + r;
            uint4 v = make_uint4(0u, 0u, 0u, 0u);
            if (gr < N)
                v = *reinterpret_cast<const uint4*>(Asrc + (size_t)gr * DIM + fc);
            *reinterpret_cast<uint4*>(Ash + r * AS + fc) = v;
        }
#pragma unroll
        for (int it = 0; it < 2; it++) {
            int r = fr + it * 32;
            uint4 v = *reinterpret_cast<const uint4*>(
                wcat + (phase * 64 + r) * DIM + fc);
            *reinterpret_cast<uint4*>(Bsh + r * BS + fc) = v;
        }
        __syncthreads();

#pragma unroll
        for (int ks = 0; ks < 4; ks++) {
            const int kb = ks * 16;
            uint32_t a0, a1, a2, a3;
            {
                uint32_t addr = (uint32_t)__cvta_generic_to_shared(
                    Ash + (warp * 16 + lrow) * AS + kb + lhalf);
                asm volatile(
                    "ldmatrix.sync.aligned.m8n8.x4.shared.b16 {%0,%1,%2,%3}, [%4];"
                    : "=r"(a0), "=r"(a1), "=r"(a2), "=r"(a3) : "r"(addr));
            }
#pragma unroll
            for (int nb = 0; nb < 4; nb++) {
                uint32_t b0, b1, b2, b3;
                uint32_t addr = (uint32_t)__cvta_generic_to_shared(
                    Bsh + (kb + lrow) * BS + nb * 16 + lhalf);
                asm volatile(
                    "ldmatrix.sync.aligned.m8n8.x4.trans.shared.b16 {%0,%1,%2,%3}, [%4];"
                    : "=r"(b0), "=r"(b1), "=r"(b2), "=r"(b3) : "r"(addr));
                asm volatile(
                    "mma.sync.aligned.m16n8k16.row.col.f32.f16.f16.f32 "
                    "{%0,%1,%2,%3}, {%4,%5,%6,%7}, {%8,%9}, {%0,%1,%2,%3};"
                    : "+f"(acc[2 * nb][0]), "+f"(acc[2 * nb][1]),
                      "+f"(acc[2 * nb][2]), "+f"(acc[2 * nb][3])
                    : "r"(a0), "r"(a1), "r"(a2), "r"(a3), "r"(b0), "r"(b1));
                asm volatile(
                    "mma.sync.aligned.m16n8k16.row.col.f32.f16.f16.f32 "
                    "{%0,%1,%2,%3}, {%4,%5,%6,%7}, {%8,%9}, {%0,%1,%2,%3};"
                    : "+f"(acc[2 * nb + 1][0]), "+f"(acc[2 * nb + 1][1]),
                      "+f"(acc[2 * nb + 1][2]), "+f"(acc[2 * nb + 1][3])
                    : "r"(a0), "r"(a1), "r"(a2), "r"(a3), "r"(b2), "r"(b3));
            }
        }
    }
    __syncthreads();

    {
        const int qrow = warp * 16 + (lane >> 2);
        const int qcol = (lane & 3) * 2;
#pragma unroll
        for (int nt = 0; nt < 8; nt++) {
            *reinterpret_cast<float2*>(&Cs[qrow * CSair + nt * 8 + qcol]) =
                make_float2(acc[nt][0], acc[nt][1]);
            *reinterpret_cast<float2*>(&Cs[(qrow + 8) * CSair + nt * 8 + qcol]) =
                make_float2(acc[nt][2], acc[nt][3]);
        }
    }
    __syncthreads();

    const int tx = tid & 15;
    const int ty = tid >> 4;
    const float4 b4 = *reinterpret_cast<const float4*>(bias + tx * 4);
#pragma unroll
    for (int rr = 0; rr < 8; rr++) {
        const int rl = ty * 8 + rr;
        const int r = rowBase + rl;
        if (r >= N) continue;
        float4 v = *reinterpret_cast<float4*>(&Cs[rl * CSair + tx * 4]);
        v.x += b4.x; v.y += b4.y; v.z += b4.z; v.w += b4.w;
        v.x = (v.x > 0.f) ? v.x : 0.01f * v.x;
        v.y = (v.y > 0.f) ? v.y : 0.01f * v.y;
        v.z = (v.z > 0.f) ? v.z : 0.01f * v.z;
        v.w = (v.w > 0.f) ? v.w : 0.01f * v.w;
        if (!pool) {
            __half2 h01 = __floats2half2_rn(v.x, v.y);
            __half2 h23 = __floats2half2_rn(v.z, v.w);
            uint2 packed = make_uint2(*reinterpret_cast<uint32_t*>(&h01),
                                      *reinterpret_cast<uint32_t*>(&h23));
            *reinterpret_cast<uint2*>(outh + (size_t)r * DIM + tx * 4) = packed;
        } else {
            int g = batch[r];
            atomicAdd(reinterpret_cast<float4*>(pooled + (size_t)g * DIM + tx * 4), v);
        }
    }
}

// ---------------------------------------------------------------------------
// final: output head + deg re-zero (maintains the deg==0 invariant).
// ---------------------------------------------------------------------------
__global__ void final_kernel(const float* __restrict__ pooled,
                             const float* __restrict__ counts,
                             const float* __restrict__ Wl,
                             const float* __restrict__ bl,
                             float* __restrict__ out,
                             int* __restrict__ deg, int N) {
    int i = blockIdx.x * blockDim.x + threadIdx.x;
    if (i < N) deg[i] = 0;
    if (i >= NGRAPH) return;
    float inv = 1.0f / fmaxf(counts[i], 1.0f);
    float acc[8];
#pragma unroll
    for (int c = 0; c < 8; c++) acc[c] = 0.f;
    for (int d = 0; d < DIM; d++) {
        float p = pooled[i * DIM + d];
#pragma unroll
        for (int c = 0; c < 8; c++) acc[c] += p * Wl[d * 8 + c];
    }
#pragma unroll
    for (int c = 0; c < 8; c++) out[i * 8 + c] = bl[c] + inv * acc[c];
}

// ---------------------------------------------------------------------------
extern "C" void kernel_launch(void* const* d_in, const int* in_sizes, int n_in,
                              void* d_out, int out_size) {
    const float* x      = (const float*)d_in[0];
    const int*   ei     = (const int*)d_in[1];
    const float* w      = (const float*)d_in[2];
    const int*   batch  = (const int*)d_in[3];
    const float* W1root = (const float*)d_in[4];
    const float* W1rel  = (const float*)d_in[5];
    const float* b1     = (const float*)d_in[6];
    const float* W2root = (const float*)d_in[7];
    const float* W2rel  = (const float*)d_in[8];
    const float* b2     = (const float*)d_in[9];
    const float* Wl     = (const float*)d_in[10];
    const float* bl     = (const float*)d_in[11];
    float* out = (float*)d_out;

    const int N = in_sizes[0] / DIM;
    const int E = in_sizes[2];

    float *pooled, *counts;
    __half *aggh, *xh, *h1h, *wcat1, *wcat2;
    int2* edges; int *deg, *rowstart, *cursor;
    unsigned long long* pub;
    cudaGetSymbolAddress((void**)&aggh,     g_aggh);
    cudaGetSymbolAddress((void**)&xh,       g_xh);
    cudaGetSymbolAddress((void**)&h1h,      g_h1h);
    cudaGetSymbolAddress((void**)&wcat1,    g_wcat1);
    cudaGetSymbolAddress((void**)&wcat2,    g_wcat2);
    cudaGetSymbolAddress((void**)&pooled,   g_pooled);
    cudaGetSymbolAddress((void**)&counts,   g_counts);
    cudaGetSymbolAddress((void**)&edges,    g_edges);
    cudaGetSymbolAddress((void**)&deg,      g_deg);
    cudaGetSymbolAddress((void**)&rowstart, g_rowstart);
    cudaGetSymbolAddress((void**)&cursor,   g_cursor);
    cudaGetSymbolAddress((void**)&pub,      g_pub);

    const int n2 = N * DIM / 2;
    const int nblk = (N + SCANB - 1) / SCANB;

    // idx0: prep (convert + wcat + histogram + zeroing)
    prep_kernel<<<(n2 + 255) / 256, 256>>>(x, xh, W1rel, W1root, W2rel, W2root,
                                           wcat1, wcat2, ei, deg, pooled, counts,
                                           pub, N, E, n2);
    // idx1: single-pass lookback scan
    scan_kernel<<<nblk, SCANB>>>(deg, rowstart, cursor, pub, N, E);
    // idx2: edge scatter (+graph counts)
    scatter_kernel<<<(E + 255) / 256, 256>>>(ei, w, cursor, edges, batch, counts, E, N);

    const int gatherBlocks = (N * 32 + 255) / 256;
    const int nodeBlocks = (N + 127) / 128;

    // idx3: gather layer 1  (ncu capture slot)
    gather_kernel<<<gatherBlocks, 256>>>(xh, edges, rowstart, aggh, N);
    // idx4: node layer 1
    node_kernel<<<nodeBlocks, 256>>>(aggh, xh, wcat1, b1,
                                     h1h, nullptr, nullptr, N, 0);
    // idx5: gather layer 2
    gather_kernel<<<gatherBlocks, 256>>>(h1h, edges, rowstart, aggh, N);
    // idx6: node layer 2 (pool epilogue)
    node_kernel<<<nodeBlocks, 256>>>(aggh, h1h, wcat2, b2,
                                     nullptr, batch, pooled, N, 1);
    // idx7: head + deg re-zero
    final_kernel<<<(N + 255) / 256, 256>>>(pooled, counts, Wl, bl, out, deg, N);
}